// round 7
// baseline (speedup 1.0000x reference)
#include <cuda_runtime.h>
#include <cstdint>

#define DD 256          // feature dim
#define HH 512          // hidden dim
#define ROWS 8          // batch rows per block
#define NT 512          // threads per block

// Packed weights: [K/4][N] float4 (float4 = 4 consecutive k for output col j)
__device__ float4 g_W1p[(DD / 4) * HH];   // K=DD, N=HH
__device__ float4 g_W2p[(HH / 4) * HH];   // K=HH, N=HH
__device__ float4 g_W3p[(HH / 4) * DD];   // K=HH, N=DD

__global__ void prep_kernel(const float* __restrict__ W1,
                            const float* __restrict__ W2,
                            const float* __restrict__ W3) {
    int idx = blockIdx.x * blockDim.x + threadIdx.x;
    int stride = gridDim.x * blockDim.x;
    float* w1p = (float*)g_W1p;
    float* w2p = (float*)g_W2p;
    float* w3p = (float*)g_W3p;
    for (int i = idx; i < HH * DD; i += stride) {       // W1 [HH][DD]
        int j = i / DD, d = i - j * DD;
        w1p[(((d >> 2) * HH) + j) * 4 + (d & 3)] = W1[i];
    }
    for (int i = idx; i < HH * HH; i += stride) {       // W2 [HH][HH]
        int j = i / HH, d = i - j * HH;
        w2p[(((d >> 2) * HH) + j) * 4 + (d & 3)] = W2[i];
    }
    for (int i = idx; i < DD * HH; i += stride) {       // W3 [DD][HH]
        int j = i / HH, d = i - j * HH;
        w3p[(((d >> 2) * DD) + j) * 4 + (d & 3)] = W3[i];
    }
}

// Layer for N==NT: thread j computes col j for all 8 rows (scalar FFMA).
// in: transposed [k][8]. out: transposed [j][8] via 2x STS.128.
template<int K, int N>
__device__ __forceinline__ void layer12(const float* __restrict__ in,
                                        float* __restrict__ outh,
                                        const float4* __restrict__ wp,
                                        const float* __restrict__ sbias,
                                        int j) {
    float bv = sbias[j];
    float a0 = bv, a1 = bv, a2 = bv, a3 = bv;
    float a4 = bv, a5 = bv, a6 = bv, a7 = bv;
    float4 wc = wp[0 * N + j];
    float4 wn = wp[1 * N + j];
#pragma unroll 1
    for (int i = 0; i < K / 4; i++) {
        int ip = (i + 2 < K / 4) ? (i + 2) : i;
        float4 wf = wp[ip * N + j];
#pragma unroll
        for (int q = 0; q < 4; q++) {
            const float* yk = in + (i * 4 + q) * ROWS;
            float4 ya = *(const float4*)(yk);
            float4 yb = *(const float4*)(yk + 4);
            float w = (q == 0) ? wc.x : (q == 1) ? wc.y : (q == 2) ? wc.z : wc.w;
            a0 = fmaf(ya.x, w, a0); a1 = fmaf(ya.y, w, a1);
            a2 = fmaf(ya.z, w, a2); a3 = fmaf(ya.w, w, a3);
            a4 = fmaf(yb.x, w, a4); a5 = fmaf(yb.y, w, a5);
            a6 = fmaf(yb.z, w, a6); a7 = fmaf(yb.w, w, a7);
        }
        wc = wn; wn = wf;
    }
    float4 r0 = { fmaxf(a0, 0.f), fmaxf(a1, 0.f), fmaxf(a2, 0.f), fmaxf(a3, 0.f) };
    float4 r1 = { fmaxf(a4, 0.f), fmaxf(a5, 0.f), fmaxf(a6, 0.f), fmaxf(a7, 0.f) };
    *(float4*)(outh + j * ROWS)     = r0;
    *(float4*)(outh + j * ROWS + 4) = r1;
}

// Layer 3: thread (j, half) computes col j for its 4 rows; result in regs.
__device__ __forceinline__ void layer3(const float* __restrict__ in,
                                       float* __restrict__ k_out,   // [4]
                                       const float* __restrict__ sbias,
                                       int j, int half) {
    const float4* __restrict__ wp = g_W3p;
    float bv = sbias[j];
    float a0 = bv, a1 = bv, a2 = bv, a3 = bv;
    const float* __restrict__ inr = in + half * 4;
    float4 wc = wp[0 * DD + j];
    float4 wn = wp[1 * DD + j];
#pragma unroll 1
    for (int i = 0; i < HH / 4; i++) {
        int ip = (i + 2 < HH / 4) ? (i + 2) : i;
        float4 wf = wp[ip * DD + j];
#pragma unroll
        for (int q = 0; q < 4; q++) {
            float4 ya = *(const float4*)(inr + (i * 4 + q) * ROWS);
            float w = (q == 0) ? wc.x : (q == 1) ? wc.y : (q == 2) ? wc.z : wc.w;
            a0 = fmaf(ya.x, w, a0); a1 = fmaf(ya.y, w, a1);
            a2 = fmaf(ya.z, w, a2); a3 = fmaf(ya.w, w, a3);
        }
        wc = wn; wn = wf;
    }
    k_out[0] = a0; k_out[1] = a1; k_out[2] = a2; k_out[3] = a3;
}

__global__ void __launch_bounds__(NT, 1)
ode_kernel(const float* __restrict__ x0,
           const int* __restrict__ Tp,
           const float* __restrict__ b1,
           const float* __restrict__ b2,
           const float* __restrict__ b3,
           float* __restrict__ out,
           int rows_total) {
    extern __shared__ float sm[];
    float* s_y   = sm;                         // DD*8, transposed [d][8]
    float* s_in  = s_y  + ROWS * DD;           // stage input buffer
    float* s_h1  = s_in + ROWS * DD;           // HH*8
    float* s_h2  = s_h1 + ROWS * HH;           // HH*8
    float* s_b1  = s_h2 + ROWS * HH;           // HH
    float* s_b2  = s_b1 + HH;                  // HH
    float* s_b3  = s_b2 + HH;                  // DD

    const int t = threadIdx.x;
    const int j3 = t & (DD - 1);
    const int half = t >> 8;
    const int row0 = blockIdx.x * ROWS;
    const int eoff = j3 * ROWS + half * 4;     // this thread's 4 state elems

    const int T = *Tp;
    const int nint = T - 1;
    const float hs = (float)(10.0 / (double)(nint * 4));

    const float A21 = (float)(1.0 / 5.0);
    const float A31 = (float)(3.0 / 40.0),       A32 = (float)(9.0 / 40.0);
    const float A41 = (float)(44.0 / 45.0),      A42 = (float)(-56.0 / 15.0),
                A43 = (float)(32.0 / 9.0);
    const float A51 = (float)(19372.0 / 6561.0), A52 = (float)(-25360.0 / 2187.0),
                A53 = (float)(64448.0 / 6561.0), A54 = (float)(-212.0 / 729.0);
    const float A61 = (float)(9017.0 / 3168.0),  A62 = (float)(-355.0 / 33.0),
                A63 = (float)(46732.0 / 5247.0), A64 = (float)(49.0 / 176.0),
                A65 = (float)(-5103.0 / 18656.0);
    const float B1 = (float)(35.0 / 384.0),  B3 = (float)(500.0 / 1113.0),
                B4 = (float)(125.0 / 192.0), B5 = (float)(-2187.0 / 6784.0),
                B6 = (float)(11.0 / 84.0);

    for (int i = t; i < HH; i += NT) { s_b1[i] = b1[i]; s_b2[i] = b2[i]; }
    for (int i = t; i < DD; i += NT) s_b3[i] = b3[i];
    for (int i = t; i < ROWS * DD; i += NT) {
        int d = i >> 3, r = i & 7;
        s_y[i] = (row0 + r < rows_total) ? x0[(size_t)(row0 + r) * DD + d] : 0.0f;
    }
    __syncthreads();

    // this thread's 4 y-elements live in registers across the whole run
    float y0[4];
    { float4 v = *(const float4*)(s_y + eoff); y0[0]=v.x; y0[1]=v.y; y0[2]=v.z; y0[3]=v.w; }

    float k1[4], k2[4], k3[4], k4[4], k5[4], k6[4];

    for (int it = 0; it < nint; it++) {
        for (int ss = 0; ss < 4; ss++) {
            // ---- stage 1: k1 = f(y) ----
            layer12<DD, HH>(s_y, s_h1, g_W1p, s_b1, t);
            __syncthreads();
            layer12<HH, HH>(s_h1, s_h2, g_W2p, s_b2, t);
            __syncthreads();
            layer3(s_h2, k1, s_b3, j3, half);
            {
                float4 v;
                v.x = fmaf(hs * A21, k1[0], y0[0]);
                v.y = fmaf(hs * A21, k1[1], y0[1]);
                v.z = fmaf(hs * A21, k1[2], y0[2]);
                v.w = fmaf(hs * A21, k1[3], y0[3]);
                *(float4*)(s_in + eoff) = v;
            }
            __syncthreads();

            // ---- stage 2 ----
            layer12<DD, HH>(s_in, s_h1, g_W1p, s_b1, t);
            __syncthreads();
            layer12<HH, HH>(s_h1, s_h2, g_W2p, s_b2, t);
            __syncthreads();
            layer3(s_h2, k2, s_b3, j3, half);
            {
                float4 v;
#pragma unroll
                for (int p = 0; p < 4; p++) {
                    float s = fmaf(A31, k1[p], A32 * k2[p]);
                    (&v.x)[p] = fmaf(hs, s, y0[p]);
                }
                *(float4*)(s_in + eoff) = v;
            }
            __syncthreads();

            // ---- stage 3 ----
            layer12<DD, HH>(s_in, s_h1, g_W1p, s_b1, t);
            __syncthreads();
            layer12<HH, HH>(s_h1, s_h2, g_W2p, s_b2, t);
            __syncthreads();
            layer3(s_h2, k3, s_b3, j3, half);
            {
                float4 v;
#pragma unroll
                for (int p = 0; p < 4; p++) {
                    float s = fmaf(A41, k1[p], fmaf(A42, k2[p], A43 * k3[p]));
                    (&v.x)[p] = fmaf(hs, s, y0[p]);
                }
                *(float4*)(s_in + eoff) = v;
            }
            __syncthreads();

            // ---- stage 4 ----
            layer12<DD, HH>(s_in, s_h1, g_W1p, s_b1, t);
            __syncthreads();
            layer12<HH, HH>(s_h1, s_h2, g_W2p, s_b2, t);
            __syncthreads();
            layer3(s_h2, k4, s_b3, j3, half);
            {
                float4 v;
#pragma unroll
                for (int p = 0; p < 4; p++) {
                    float s = fmaf(A51, k1[p],
                              fmaf(A52, k2[p],
                              fmaf(A53, k3[p], A54 * k4[p])));
                    (&v.x)[p] = fmaf(hs, s, y0[p]);
                }
                *(float4*)(s_in + eoff) = v;
            }
            __syncthreads();

            // ---- stage 5 ----
            layer12<DD, HH>(s_in, s_h1, g_W1p, s_b1, t);
            __syncthreads();
            layer12<HH, HH>(s_h1, s_h2, g_W2p, s_b2, t);
            __syncthreads();
            layer3(s_h2, k5, s_b3, j3, half);
            {
                float4 v;
#pragma unroll
                for (int p = 0; p < 4; p++) {
                    float s = fmaf(A61, k1[p],
                              fmaf(A62, k2[p],
                              fmaf(A63, k3[p],
                              fmaf(A64, k4[p], A65 * k5[p]))));
                    (&v.x)[p] = fmaf(hs, s, y0[p]);
                }
                *(float4*)(s_in + eoff) = v;
            }
            __syncthreads();

            // ---- stage 6: k6, then y update ----
            layer12<DD, HH>(s_in, s_h1, g_W1p, s_b1, t);
            __syncthreads();
            layer12<HH, HH>(s_h1, s_h2, g_W2p, s_b2, t);
            __syncthreads();
            layer3(s_h2, k6, s_b3, j3, half);
            {
                float4 v;
#pragma unroll
                for (int p = 0; p < 4; p++) {
                    float s = fmaf(B1, k1[p],
                              fmaf(B3, k3[p],
                              fmaf(B4, k4[p],
                              fmaf(B5, k5[p], B6 * k6[p]))));
                    y0[p] = fmaf(hs, s, y0[p]);
                    (&v.x)[p] = y0[p];
                }
                *(float4*)(s_y + eoff) = v;
            }
            __syncthreads();
        }
        // store y for this interval straight from registers:
        // element (d=j3, r=half*4+p) -> out[(row0+r)*nint + it][d]
#pragma unroll
        for (int p = 0; p < 4; p++) {
            int b = row0 + half * 4 + p;
            if (b < rows_total)
                out[((size_t)b * nint + it) * DD + j3] = y0[p];
        }
    }
}

extern "C" void kernel_launch(void* const* d_in, const int* in_sizes, int n_in,
                              void* d_out, int out_size) {
    const float* x0 = (const float*)d_in[0];
    const int*   Tp = (const int*)d_in[1];
    const float* W1 = (const float*)d_in[2];
    const float* b1 = (const float*)d_in[3];
    const float* W2 = (const float*)d_in[4];
    const float* b2 = (const float*)d_in[5];
    const float* W3 = (const float*)d_in[6];
    const float* b3 = (const float*)d_in[7];
    float* out = (float*)d_out;

    int rows_total = in_sizes[0] / DD;          // B
    int nblocks = (rows_total + ROWS - 1) / ROWS;

    size_t smem = (size_t)(2 * ROWS * DD + 2 * ROWS * HH + 2 * HH + DD) * sizeof(float);
    cudaFuncSetAttribute(ode_kernel, cudaFuncAttributeMaxDynamicSharedMemorySize,
                         (int)smem);

    prep_kernel<<<64, 256>>>(W1, W2, W3);
    ode_kernel<<<nblocks, NT, smem>>>(x0, Tp, b1, b2, b3, out, rows_total);
}

// round 9
// speedup vs baseline: 1.0741x; 1.0741x over previous
#include <cuda_runtime.h>
#include <cstdint>

#define DD 256          // feature dim
#define HH 512          // hidden dim
#define HN 256          // HH/2
#define ROWS 8          // batch rows per block
#define NT 512          // threads per block

// Packed weights: [K/4][N] float4 (float4 = 4 consecutive k for output col j)
__device__ float4 g_W1p[(DD / 4) * HH];   // K=DD, N=HH
__device__ float4 g_W2p[(HH / 4) * HH];   // K=HH, N=HH
__device__ float4 g_W3p[(HH / 4) * DD];   // K=HH, N=DD

__global__ void prep_kernel(const float* __restrict__ W1,
                            const float* __restrict__ W2,
                            const float* __restrict__ W3) {
    int idx = blockIdx.x * blockDim.x + threadIdx.x;
    int stride = gridDim.x * blockDim.x;
    float* w1p = (float*)g_W1p;
    float* w2p = (float*)g_W2p;
    float* w3p = (float*)g_W3p;
    for (int i = idx; i < HH * DD; i += stride) {       // W1 [HH][DD]
        int j = i / DD, d = i - j * DD;
        w1p[(((d >> 2) * HH) + j) * 4 + (d & 3)] = W1[i];
    }
    for (int i = idx; i < HH * HH; i += stride) {       // W2 [HH][HH]
        int j = i / HH, d = i - j * HH;
        w2p[(((d >> 2) * HH) + j) * 4 + (d & 3)] = W2[i];
    }
    for (int i = idx; i < DD * HH; i += stride) {       // W3 [DD][HH]
        int j = i / HH, d = i - j * HH;
        w3p[(((d >> 2) * DD) + j) * 4 + (d & 3)] = W3[i];
    }
}

// One 4-k step: 4 rows x 2 cols = 32 FMA, 4 broadcast LDS.128.
__device__ __forceinline__ void l12_step(const float* __restrict__ py,
                                         const float4 wa, const float4 wb,
                                         float* __restrict__ accA,
                                         float* __restrict__ accB) {
#pragma unroll
    for (int q = 0; q < 4; q++) {
        float4 ya = *(const float4*)(py + q * 8);
        float wA = (q == 0) ? wa.x : (q == 1) ? wa.y : (q == 2) ? wa.z : wa.w;
        float wB = (q == 0) ? wb.x : (q == 1) ? wb.y : (q == 2) ? wb.z : wb.w;
        accA[0] = fmaf(ya.x, wA, accA[0]); accA[1] = fmaf(ya.y, wA, accA[1]);
        accA[2] = fmaf(ya.z, wA, accA[2]); accA[3] = fmaf(ya.w, wA, accA[3]);
        accB[0] = fmaf(ya.x, wB, accB[0]); accB[1] = fmaf(ya.y, wB, accB[1]);
        accB[2] = fmaf(ya.z, wB, accB[2]); accB[3] = fmaf(ya.w, wB, accB[3]);
    }
}

// Layers 1/2: thread (j0, half) computes cols {j0, j0+HN} for rows half*4..+3.
// in/out transposed [k][8]. Steady loop has no conditionals; last 2 iters peeled.
template<int K, int N>
__device__ __forceinline__ void layer12(const float* __restrict__ in,
                                        float* __restrict__ outh,
                                        const float4* __restrict__ wp,
                                        const float* __restrict__ sbias,
                                        int j0, int half) {
    constexpr int K4 = K / 4;
    float accA[4], accB[4];
    const float bA = sbias[j0], bB = sbias[j0 + HN];
#pragma unroll
    for (int r = 0; r < 4; r++) { accA[r] = bA; accB[r] = bB; }

    const float* py = in + half * 4;
    const float4* pw = wp + j0;
    float4 wac = pw[0], wbc = pw[HN];
    float4 wan = pw[N], wbn = pw[N + HN];
    pw += 2 * N;
#pragma unroll 1
    for (int i = 0; i < K4 - 2; i++) {
        float4 waf = pw[0], wbf = pw[HN];
        pw += N;
        l12_step(py, wac, wbc, accA, accB);
        py += 32;
        wac = wan; wan = waf;
        wbc = wbn; wbn = wbf;
    }
    l12_step(py, wac, wbc, accA, accB);
    py += 32;
    l12_step(py, wan, wbn, accA, accB);

    float4 r0 = { fmaxf(accA[0], 0.f), fmaxf(accA[1], 0.f),
                  fmaxf(accA[2], 0.f), fmaxf(accA[3], 0.f) };
    float4 r1 = { fmaxf(accB[0], 0.f), fmaxf(accB[1], 0.f),
                  fmaxf(accB[2], 0.f), fmaxf(accB[3], 0.f) };
    *(float4*)(outh + j0 * ROWS + half * 4) = r0;
    *(float4*)(outh + (j0 + HN) * ROWS + half * 4) = r1;
}

__device__ __forceinline__ void l3_step(const float* __restrict__ py,
                                        const float4 w,
                                        float* __restrict__ acc) {
#pragma unroll
    for (int q = 0; q < 4; q++) {
        float4 ya = *(const float4*)(py + q * 8);
        float wv = (q == 0) ? w.x : (q == 1) ? w.y : (q == 2) ? w.z : w.w;
        acc[0] = fmaf(ya.x, wv, acc[0]); acc[1] = fmaf(ya.y, wv, acc[1]);
        acc[2] = fmaf(ya.z, wv, acc[2]); acc[3] = fmaf(ya.w, wv, acc[3]);
    }
}

// Layer 3: thread (j, half) computes col j for its 4 rows; result in regs.
__device__ __forceinline__ void layer3(const float* __restrict__ in,
                                       float* __restrict__ k_out,   // [4]
                                       const float* __restrict__ sbias,
                                       int j, int half) {
    constexpr int K4 = HH / 4;
    float acc[4];
    const float bv = sbias[j];
#pragma unroll
    for (int r = 0; r < 4; r++) acc[r] = bv;

    const float* py = in + half * 4;
    const float4* pw = g_W3p + j;
    float4 wc = pw[0];
    float4 wn = pw[DD];
    pw += 2 * DD;
#pragma unroll 1
    for (int i = 0; i < K4 - 2; i++) {
        float4 wf = pw[0];
        pw += DD;
        l3_step(py, wc, acc);
        py += 32;
        wc = wn; wn = wf;
    }
    l3_step(py, wc, acc);
    py += 32;
    l3_step(py, wn, acc);

    k_out[0] = acc[0]; k_out[1] = acc[1]; k_out[2] = acc[2]; k_out[3] = acc[3];
}

__global__ void __launch_bounds__(NT, 1)
ode_kernel(const float* __restrict__ x0,
           const int* __restrict__ Tp,
           const float* __restrict__ b1,
           const float* __restrict__ b2,
           const float* __restrict__ b3,
           float* __restrict__ out,
           int rows_total) {
    extern __shared__ float sm[];
    float* s_y   = sm;                         // DD*8, transposed [d][8]
    float* s_in  = s_y  + ROWS * DD;           // stage input buffer
    float* s_h1  = s_in + ROWS * DD;           // HH*8
    float* s_h2  = s_h1 + ROWS * HH;           // HH*8
    float* s_b1  = s_h2 + ROWS * HH;           // HH
    float* s_b2  = s_b1 + HH;                  // HH
    float* s_b3  = s_b2 + HH;                  // DD

    const int t = threadIdx.x;
    const int j0 = t & 255;                    // col group (layers 1/2: cols j0, j0+HN)
    const int half = t >> 8;                   // row half (rows half*4..half*4+3)
    const int row0 = blockIdx.x * ROWS;
    const int eoff = j0 * ROWS + half * 4;     // this thread's 4 state elems (d=j0)

    const int T = *Tp;
    const int nint = T - 1;
    const float hs = (float)(10.0 / (double)(nint * 4));

    const float A21 = (float)(1.0 / 5.0);
    const float A31 = (float)(3.0 / 40.0),       A32 = (float)(9.0 / 40.0);
    const float A41 = (float)(44.0 / 45.0),      A42 = (float)(-56.0 / 15.0),
                A43 = (float)(32.0 / 9.0);
    const float A51 = (float)(19372.0 / 6561.0), A52 = (float)(-25360.0 / 2187.0),
                A53 = (float)(64448.0 / 6561.0), A54 = (float)(-212.0 / 729.0);
    const float A61 = (float)(9017.0 / 3168.0),  A62 = (float)(-355.0 / 33.0),
                A63 = (float)(46732.0 / 5247.0), A64 = (float)(49.0 / 176.0),
                A65 = (float)(-5103.0 / 18656.0);
    const float B1 = (float)(35.0 / 384.0),  B3 = (float)(500.0 / 1113.0),
                B4 = (float)(125.0 / 192.0), B5 = (float)(-2187.0 / 6784.0),
                B6 = (float)(11.0 / 84.0);

    for (int i = t; i < HH; i += NT) { s_b1[i] = b1[i]; s_b2[i] = b2[i]; }
    for (int i = t; i < DD; i += NT) s_b3[i] = b3[i];
    for (int i = t; i < ROWS * DD; i += NT) {
        int d = i >> 3, r = i & 7;
        s_y[i] = (row0 + r < rows_total) ? x0[(size_t)(row0 + r) * DD + d] : 0.0f;
    }
    __syncthreads();

    // this thread's 4 y-elements live in registers across the whole run
    float y0[4];
    { float4 v = *(const float4*)(s_y + eoff); y0[0]=v.x; y0[1]=v.y; y0[2]=v.z; y0[3]=v.w; }

    float k1[4], k2[4], k3[4], k4[4], k5[4], k6[4];

    for (int it = 0; it < nint; it++) {
        for (int ss = 0; ss < 4; ss++) {
            // ---- stage 1: k1 = f(y) ----
            layer12<DD, HH>(s_y, s_h1, g_W1p, s_b1, j0, half);
            __syncthreads();
            layer12<HH, HH>(s_h1, s_h2, g_W2p, s_b2, j0, half);
            __syncthreads();
            layer3(s_h2, k1, s_b3, j0, half);
            {
                float4 v;
#pragma unroll
                for (int p = 0; p < 4; p++)
                    (&v.x)[p] = fmaf(hs * A21, k1[p], y0[p]);
                *(float4*)(s_in + eoff) = v;
            }
            __syncthreads();

            // ---- stage 2 ----
            layer12<DD, HH>(s_in, s_h1, g_W1p, s_b1, j0, half);
            __syncthreads();
            layer12<HH, HH>(s_h1, s_h2, g_W2p, s_b2, j0, half);
            __syncthreads();
            layer3(s_h2, k2, s_b3, j0, half);
            {
                float4 v;
#pragma unroll
                for (int p = 0; p < 4; p++) {
                    float s = fmaf(A31, k1[p], A32 * k2[p]);
                    (&v.x)[p] = fmaf(hs, s, y0[p]);
                }
                *(float4*)(s_in + eoff) = v;
            }
            __syncthreads();

            // ---- stage 3 ----
            layer12<DD, HH>(s_in, s_h1, g_W1p, s_b1, j0, half);
            __syncthreads();
            layer12<HH, HH>(s_h1, s_h2, g_W2p, s_b2, j0, half);
            __syncthreads();
            layer3(s_h2, k3, s_b3, j0, half);
            {
                float4 v;
#pragma unroll
                for (int p = 0; p < 4; p++) {
                    float s = fmaf(A41, k1[p], fmaf(A42, k2[p], A43 * k3[p]));
                    (&v.x)[p] = fmaf(hs, s, y0[p]);
                }
                *(float4*)(s_in + eoff) = v;
            }
            __syncthreads();

            // ---- stage 4 ----
            layer12<DD, HH>(s_in, s_h1, g_W1p, s_b1, j0, half);
            __syncthreads();
            layer12<HH, HH>(s_h1, s_h2, g_W2p, s_b2, j0, half);
            __syncthreads();
            layer3(s_h2, k4, s_b3, j0, half);
            {
                float4 v;
#pragma unroll
                for (int p = 0; p < 4; p++) {
                    float s = fmaf(A51, k1[p],
                              fmaf(A52, k2[p],
                              fmaf(A53, k3[p], A54 * k4[p])));
                    (&v.x)[p] = fmaf(hs, s, y0[p]);
                }
                *(float4*)(s_in + eoff) = v;
            }
            __syncthreads();

            // ---- stage 5 ----
            layer12<DD, HH>(s_in, s_h1, g_W1p, s_b1, j0, half);
            __syncthreads();
            layer12<HH, HH>(s_h1, s_h2, g_W2p, s_b2, j0, half);
            __syncthreads();
            layer3(s_h2, k5, s_b3, j0, half);
            {
                float4 v;
#pragma unroll
                for (int p = 0; p < 4; p++) {
                    float s = fmaf(A61, k1[p],
                              fmaf(A62, k2[p],
                              fmaf(A63, k3[p],
                              fmaf(A64, k4[p], A65 * k5[p]))));
                    (&v.x)[p] = fmaf(hs, s, y0[p]);
                }
                *(float4*)(s_in + eoff) = v;
            }
            __syncthreads();

            // ---- stage 6: k6, then y update ----
            layer12<DD, HH>(s_in, s_h1, g_W1p, s_b1, j0, half);
            __syncthreads();
            layer12<HH, HH>(s_h1, s_h2, g_W2p, s_b2, j0, half);
            __syncthreads();
            layer3(s_h2, k6, s_b3, j0, half);
            {
                float4 v;
#pragma unroll
                for (int p = 0; p < 4; p++) {
                    float s = fmaf(B1, k1[p],
                              fmaf(B3, k3[p],
                              fmaf(B4, k4[p],
                              fmaf(B5, k5[p], B6 * k6[p]))));
                    y0[p] = fmaf(hs, s, y0[p]);
                    (&v.x)[p] = y0[p];
                }
                *(float4*)(s_y + eoff) = v;
            }
            __syncthreads();
        }
        // store y for this interval straight from registers:
        // element (d=j0, r=half*4+p) -> out[(row0+r)*nint + it][d]
#pragma unroll
        for (int p = 0; p < 4; p++) {
            int b = row0 + half * 4 + p;
            if (b < rows_total)
                out[((size_t)b * nint + it) * DD + j0] = y0[p];
        }
    }
}

extern "C" void kernel_launch(void* const* d_in, const int* in_sizes, int n_in,
                              void* d_out, int out_size) {
    const float* x0 = (const float*)d_in[0];
    const int*   Tp = (const int*)d_in[1];
    const float* W1 = (const float*)d_in[2];
    const float* b1 = (const float*)d_in[3];
    const float* W2 = (const float*)d_in[4];
    const float* b2 = (const float*)d_in[5];
    const float* W3 = (const float*)d_in[6];
    const float* b3 = (const float*)d_in[7];
    float* out = (float*)d_out;

    int rows_total = in_sizes[0] / DD;          // B
    int nblocks = (rows_total + ROWS - 1) / ROWS;

    size_t smem = (size_t)(2 * ROWS * DD + 2 * ROWS * HH + 2 * HH + DD) * sizeof(float);
    cudaFuncSetAttribute(ode_kernel, cudaFuncAttributeMaxDynamicSharedMemorySize,
                         (int)smem);

    prep_kernel<<<64, 256>>>(W1, W2, W3);
    ode_kernel<<<nblocks, NT, smem>>>(x0, Tp, b1, b2, b3, out, rows_total);
}

// round 11
// speedup vs baseline: 1.2786x; 1.1904x over previous
#include <cuda_runtime.h>
#include <cstdint>

#define DD 256          // feature dim
#define HH 512          // hidden dim
#define HN 256          // HH/2
#define ROWS 8          // batch rows per block
#define NT 512          // threads per block

// Packed weights: [K/4][N] float4 (float4 = 4 consecutive k for output col j)
__device__ float4 g_W1p[(DD / 4) * HH];   // K=DD, N=HH
__device__ float4 g_W2p[(HH / 4) * HH];   // K=HH, N=HH
__device__ float4 g_W3p[(HH / 4) * DD];   // K=HH, N=DD

__global__ void prep_kernel(const float* __restrict__ W1,
                            const float* __restrict__ W2,
                            const float* __restrict__ W3) {
    int idx = blockIdx.x * blockDim.x + threadIdx.x;
    int stride = gridDim.x * blockDim.x;
    float* w1p = (float*)g_W1p;
    float* w2p = (float*)g_W2p;
    float* w3p = (float*)g_W3p;
    for (int i = idx; i < HH * DD; i += stride) {       // W1 [HH][DD]
        int j = i / DD, d = i - j * DD;
        w1p[(((d >> 2) * HH) + j) * 4 + (d & 3)] = W1[i];
    }
    for (int i = idx; i < HH * HH; i += stride) {       // W2 [HH][HH]
        int j = i / HH, d = i - j * HH;
        w2p[(((d >> 2) * HH) + j) * 4 + (d & 3)] = W2[i];
    }
    for (int i = idx; i < DD * HH; i += stride) {       // W3 [DD][HH]
        int j = i / HH, d = i - j * HH;
        w3p[(((d >> 2) * DD) + j) * 4 + (d & 3)] = W3[i];
    }
}

// One 4-k step: 4 rows x 2 cols = 32 FMA, 4 broadcast LDS.128.
__device__ __forceinline__ void l12_step(const float* __restrict__ py,
                                         const float4 wa, const float4 wb,
                                         float* __restrict__ accA,
                                         float* __restrict__ accB) {
#pragma unroll
    for (int q = 0; q < 4; q++) {
        float4 ya = *(const float4*)(py + q * 8);
        float wA = (q == 0) ? wa.x : (q == 1) ? wa.y : (q == 2) ? wa.z : wa.w;
        float wB = (q == 0) ? wb.x : (q == 1) ? wb.y : (q == 2) ? wb.z : wb.w;
        accA[0] = fmaf(ya.x, wA, accA[0]); accA[1] = fmaf(ya.y, wA, accA[1]);
        accA[2] = fmaf(ya.z, wA, accA[2]); accA[3] = fmaf(ya.w, wA, accA[3]);
        accB[0] = fmaf(ya.x, wB, accB[0]); accB[1] = fmaf(ya.y, wB, accB[1]);
        accB[2] = fmaf(ya.z, wB, accB[2]); accB[3] = fmaf(ya.w, wB, accB[3]);
    }
}

// Layers 1/2: thread (j0, half) computes cols {j0, j0+HN} for rows half*4..+3.
// Plain indexed loads, no rotation, no peeling: unroll-2 gives SSA weight regs
// (zero MOVs); latency covered by 4-warps/SMSP interleaving.
template<int K, int N>
__device__ __forceinline__ void layer12(const float* __restrict__ in,
                                        float* __restrict__ outh,
                                        const float4* __restrict__ wp,
                                        const float* __restrict__ sbias,
                                        int j0, int half) {
    constexpr int K4 = K / 4;
    float accA[4], accB[4];
    const float bA = sbias[j0], bB = sbias[j0 + HN];
#pragma unroll
    for (int r = 0; r < 4; r++) { accA[r] = bA; accB[r] = bB; }

    const float* py = in + half * 4;
    const float4* pw = wp + j0;
#pragma unroll 2
    for (int i = 0; i < K4; i++) {
        float4 wa = pw[0];
        float4 wb = pw[HN];
        pw += N;
        l12_step(py, wa, wb, accA, accB);
        py += 32;
    }

    float4 r0 = { fmaxf(accA[0], 0.f), fmaxf(accA[1], 0.f),
                  fmaxf(accA[2], 0.f), fmaxf(accA[3], 0.f) };
    float4 r1 = { fmaxf(accB[0], 0.f), fmaxf(accB[1], 0.f),
                  fmaxf(accB[2], 0.f), fmaxf(accB[3], 0.f) };
    *(float4*)(outh + j0 * ROWS + half * 4) = r0;
    *(float4*)(outh + (j0 + HN) * ROWS + half * 4) = r1;
}

__device__ __forceinline__ void l3_step(const float* __restrict__ py,
                                        const float4 w,
                                        float* __restrict__ acc) {
#pragma unroll
    for (int q = 0; q < 4; q++) {
        float4 ya = *(const float4*)(py + q * 8);
        float wv = (q == 0) ? w.x : (q == 1) ? w.y : (q == 2) ? w.z : w.w;
        acc[0] = fmaf(ya.x, wv, acc[0]); acc[1] = fmaf(ya.y, wv, acc[1]);
        acc[2] = fmaf(ya.z, wv, acc[2]); acc[3] = fmaf(ya.w, wv, acc[3]);
    }
}

// Layer 3: thread (j, half) computes col j for its 4 rows; result in regs.
__device__ __forceinline__ void layer3(const float* __restrict__ in,
                                       float* __restrict__ k_out,   // [4]
                                       const float* __restrict__ sbias,
                                       int j, int half) {
    constexpr int K4 = HH / 4;
    float acc[4];
    const float bv = sbias[j];
#pragma unroll
    for (int r = 0; r < 4; r++) acc[r] = bv;

    const float* py = in + half * 4;
    const float4* pw = g_W3p + j;
#pragma unroll 2
    for (int i = 0; i < K4; i++) {
        float4 w = pw[0];
        pw += DD;
        l3_step(py, w, acc);
        py += 32;
    }

    k_out[0] = acc[0]; k_out[1] = acc[1]; k_out[2] = acc[2]; k_out[3] = acc[3];
}

__global__ void __launch_bounds__(NT, 1)
ode_kernel(const float* __restrict__ x0,
           const int* __restrict__ Tp,
           const float* __restrict__ b1,
           const float* __restrict__ b2,
           const float* __restrict__ b3,
           float* __restrict__ out,
           int rows_total) {
    extern __shared__ float sm[];
    float* s_y   = sm;                         // DD*8, transposed [d][8]
    float* s_in  = s_y  + ROWS * DD;           // stage input buffer
    float* s_h1  = s_in + ROWS * DD;           // HH*8
    float* s_h2  = s_h1 + ROWS * HH;           // HH*8
    float* s_b1  = s_h2 + ROWS * HH;           // HH
    float* s_b2  = s_b1 + HH;                  // HH
    float* s_b3  = s_b2 + HH;                  // DD

    const int t = threadIdx.x;
    const int j0 = t & 255;                    // col group (layers 1/2: cols j0, j0+HN)
    const int half = t >> 8;                   // row half (rows half*4..half*4+3)
    const int row0 = blockIdx.x * ROWS;
    const int eoff = j0 * ROWS + half * 4;     // this thread's 4 state elems (d=j0)

    const int T = *Tp;
    const int nint = T - 1;
    const float hs = (float)(10.0 / (double)(nint * 4));

    const float A21 = (float)(1.0 / 5.0);
    const float A31 = (float)(3.0 / 40.0),       A32 = (float)(9.0 / 40.0);
    const float A41 = (float)(44.0 / 45.0),      A42 = (float)(-56.0 / 15.0),
                A43 = (float)(32.0 / 9.0);
    const float A51 = (float)(19372.0 / 6561.0), A52 = (float)(-25360.0 / 2187.0),
                A53 = (float)(64448.0 / 6561.0), A54 = (float)(-212.0 / 729.0);
    const float A61 = (float)(9017.0 / 3168.0),  A62 = (float)(-355.0 / 33.0),
                A63 = (float)(46732.0 / 5247.0), A64 = (float)(49.0 / 176.0),
                A65 = (float)(-5103.0 / 18656.0);
    const float B1 = (float)(35.0 / 384.0),  B3 = (float)(500.0 / 1113.0),
                B4 = (float)(125.0 / 192.0), B5 = (float)(-2187.0 / 6784.0),
                B6 = (float)(11.0 / 84.0);

    for (int i = t; i < HH; i += NT) { s_b1[i] = b1[i]; s_b2[i] = b2[i]; }
    for (int i = t; i < DD; i += NT) s_b3[i] = b3[i];
    for (int i = t; i < ROWS * DD; i += NT) {
        int d = i >> 3, r = i & 7;
        s_y[i] = (row0 + r < rows_total) ? x0[(size_t)(row0 + r) * DD + d] : 0.0f;
    }
    __syncthreads();

    // this thread's 4 y-elements live in registers across the whole run
    float y0[4];
    { float4 v = *(const float4*)(s_y + eoff); y0[0]=v.x; y0[1]=v.y; y0[2]=v.z; y0[3]=v.w; }

    float k1[4], k2[4], k3[4], k4[4], k5[4], k6[4];

    for (int it = 0; it < nint; it++) {
        for (int ss = 0; ss < 4; ss++) {
            // ---- stage 1: k1 = f(y) ----
            layer12<DD, HH>(s_y, s_h1, g_W1p, s_b1, j0, half);
            __syncthreads();
            layer12<HH, HH>(s_h1, s_h2, g_W2p, s_b2, j0, half);
            __syncthreads();
            layer3(s_h2, k1, s_b3, j0, half);
            {
                float4 v;
#pragma unroll
                for (int p = 0; p < 4; p++)
                    (&v.x)[p] = fmaf(hs * A21, k1[p], y0[p]);
                *(float4*)(s_in + eoff) = v;
            }
            __syncthreads();

            // ---- stage 2 ----
            layer12<DD, HH>(s_in, s_h1, g_W1p, s_b1, j0, half);
            __syncthreads();
            layer12<HH, HH>(s_h1, s_h2, g_W2p, s_b2, j0, half);
            __syncthreads();
            layer3(s_h2, k2, s_b3, j0, half);
            {
                float4 v;
#pragma unroll
                for (int p = 0; p < 4; p++) {
                    float s = fmaf(A31, k1[p], A32 * k2[p]);
                    (&v.x)[p] = fmaf(hs, s, y0[p]);
                }
                *(float4*)(s_in + eoff) = v;
            }
            __syncthreads();

            // ---- stage 3 ----
            layer12<DD, HH>(s_in, s_h1, g_W1p, s_b1, j0, half);
            __syncthreads();
            layer12<HH, HH>(s_h1, s_h2, g_W2p, s_b2, j0, half);
            __syncthreads();
            layer3(s_h2, k3, s_b3, j0, half);
            {
                float4 v;
#pragma unroll
                for (int p = 0; p < 4; p++) {
                    float s = fmaf(A41, k1[p], fmaf(A42, k2[p], A43 * k3[p]));
                    (&v.x)[p] = fmaf(hs, s, y0[p]);
                }
                *(float4*)(s_in + eoff) = v;
            }
            __syncthreads();

            // ---- stage 4 ----
            layer12<DD, HH>(s_in, s_h1, g_W1p, s_b1, j0, half);
            __syncthreads();
            layer12<HH, HH>(s_h1, s_h2, g_W2p, s_b2, j0, half);
            __syncthreads();
            layer3(s_h2, k4, s_b3, j0, half);
            {
                float4 v;
#pragma unroll
                for (int p = 0; p < 4; p++) {
                    float s = fmaf(A51, k1[p],
                              fmaf(A52, k2[p],
                              fmaf(A53, k3[p], A54 * k4[p])));
                    (&v.x)[p] = fmaf(hs, s, y0[p]);
                }
                *(float4*)(s_in + eoff) = v;
            }
            __syncthreads();

            // ---- stage 5 ----
            layer12<DD, HH>(s_in, s_h1, g_W1p, s_b1, j0, half);
            __syncthreads();
            layer12<HH, HH>(s_h1, s_h2, g_W2p, s_b2, j0, half);
            __syncthreads();
            layer3(s_h2, k5, s_b3, j0, half);
            {
                float4 v;
#pragma unroll
                for (int p = 0; p < 4; p++) {
                    float s = fmaf(A61, k1[p],
                              fmaf(A62, k2[p],
                              fmaf(A63, k3[p],
                              fmaf(A64, k4[p], A65 * k5[p]))));
                    (&v.x)[p] = fmaf(hs, s, y0[p]);
                }
                *(float4*)(s_in + eoff) = v;
            }
            __syncthreads();

            // ---- stage 6: k6, then y update ----
            layer12<DD, HH>(s_in, s_h1, g_W1p, s_b1, j0, half);
            __syncthreads();
            layer12<HH, HH>(s_h1, s_h2, g_W2p, s_b2, j0, half);
            __syncthreads();
            layer3(s_h2, k6, s_b3, j0, half);
            {
                float4 v;
#pragma unroll
                for (int p = 0; p < 4; p++) {
                    float s = fmaf(B1, k1[p],
                              fmaf(B3, k3[p],
                              fmaf(B4, k4[p],
                              fmaf(B5, k5[p], B6 * k6[p]))));
                    y0[p] = fmaf(hs, s, y0[p]);
                    (&v.x)[p] = y0[p];
                }
                *(float4*)(s_y + eoff) = v;
            }
            __syncthreads();
        }
        // store y for this interval straight from registers:
        // element (d=j0, r=half*4+p) -> out[(row0+r)*nint + it][d]
#pragma unroll
        for (int p = 0; p < 4; p++) {
            int b = row0 + half * 4 + p;
            if (b < rows_total)
                out[((size_t)b * nint + it) * DD + j0] = y0[p];
        }
    }
}

extern "C" void kernel_launch(void* const* d_in, const int* in_sizes, int n_in,
                              void* d_out, int out_size) {
    const float* x0 = (const float*)d_in[0];
    const int*   Tp = (const int*)d_in[1];
    const float* W1 = (const float*)d_in[2];
    const float* b1 = (const float*)d_in[3];
    const float* W2 = (const float*)d_in[4];
    const float* b2 = (const float*)d_in[5];
    const float* W3 = (const float*)d_in[6];
    const float* b3 = (const float*)d_in[7];
    float* out = (float*)d_out;

    int rows_total = in_sizes[0] / DD;          // B
    int nblocks = (rows_total + ROWS - 1) / ROWS;

    size_t smem = (size_t)(2 * ROWS * DD + 2 * ROWS * HH + 2 * HH + DD) * sizeof(float);
    cudaFuncSetAttribute(ode_kernel, cudaFuncAttributeMaxDynamicSharedMemorySize,
                         (int)smem);

    prep_kernel<<<64, 256>>>(W1, W2, W3);
    ode_kernel<<<nblocks, NT, smem>>>(x0, Tp, b1, b2, b3, out, rows_total);
}

// round 17
// speedup vs baseline: 1.3521x; 1.0575x over previous
#include <cuda_runtime.h>
#include <cstdint>

#define DD 256          // feature dim
#define HH 512          // hidden dim
#define HN 256          // HH/2
#define ROWS 8          // batch rows per block
#define NT 512          // threads per block

// Packed weights: [K/4][N] float4 (float4 = 4 consecutive k for output col j)
__device__ float4 g_W1p[(DD / 4) * HH];   // K=DD, N=HH
__device__ float4 g_W2p[(HH / 4) * HH];   // K=HH, N=HH
__device__ float4 g_W3p[(HH / 4) * DD];   // K=HH, N=DD

__global__ void prep_kernel(const float* __restrict__ W1,
                            const float* __restrict__ W2,
                            const float* __restrict__ W3) {
    int idx = blockIdx.x * blockDim.x + threadIdx.x;
    int stride = gridDim.x * blockDim.x;
    float* w1p = (float*)g_W1p;
    float* w2p = (float*)g_W2p;
    float* w3p = (float*)g_W3p;
    for (int i = idx; i < HH * DD; i += stride) {       // W1 [HH][DD]
        int j = i / DD, d = i - j * DD;
        w1p[(((d >> 2) * HH) + j) * 4 + (d & 3)] = W1[i];
    }
    for (int i = idx; i < HH * HH; i += stride) {       // W2 [HH][HH]
        int j = i / HH, d = i - j * HH;
        w2p[(((d >> 2) * HH) + j) * 4 + (d & 3)] = W2[i];
    }
    for (int i = idx; i < DD * HH; i += stride) {       // W3 [DD][HH]
        int j = i / HH, d = i - j * HH;
        w3p[(((d >> 2) * DD) + j) * 4 + (d & 3)] = W3[i];
    }
}

// One 4-k step: 4 rows x 2 cols = 32 FMA, 4 broadcast LDS.128.
__device__ __forceinline__ void l12_step(const float* __restrict__ py,
                                         const float4 wa, const float4 wb,
                                         float* __restrict__ accA,
                                         float* __restrict__ accB) {
#pragma unroll
    for (int q = 0; q < 4; q++) {
        float4 ya = *(const float4*)(py + q * 8);
        float wA = (q == 0) ? wa.x : (q == 1) ? wa.y : (q == 2) ? wa.z : wa.w;
        float wB = (q == 0) ? wb.x : (q == 1) ? wb.y : (q == 2) ? wb.z : wb.w;
        accA[0] = fmaf(ya.x, wA, accA[0]); accA[1] = fmaf(ya.y, wA, accA[1]);
        accA[2] = fmaf(ya.z, wA, accA[2]); accA[3] = fmaf(ya.w, wA, accA[3]);
        accB[0] = fmaf(ya.x, wB, accB[0]); accB[1] = fmaf(ya.y, wB, accB[1]);
        accB[2] = fmaf(ya.z, wB, accB[2]); accB[3] = fmaf(ya.w, wB, accB[3]);
    }
}

// Layers 1/2: thread (j0, half) computes cols {j0, j0+HN} for rows half*4..+3.
// Plain indexed loads, no rotation: unroll-4 gives SSA weight regs (zero MOVs)
// and a ~4-iteration load-hoist window (> L2 latency at 4 warps/SMSP).
template<int K, int N>
__device__ __forceinline__ void layer12(const float* __restrict__ in,
                                        float* __restrict__ outh,
                                        const float4* __restrict__ wp,
                                        const float* __restrict__ sbias,
                                        int j0, int half) {
    constexpr int K4 = K / 4;
    float accA[4], accB[4];
    const float bA = sbias[j0], bB = sbias[j0 + HN];
#pragma unroll
    for (int r = 0; r < 4; r++) { accA[r] = bA; accB[r] = bB; }

    const float* py = in + half * 4;
    const float4* pw = wp + j0;
#pragma unroll 4
    for (int i = 0; i < K4; i++) {
        float4 wa = pw[0];
        float4 wb = pw[HN];
        pw += N;
        l12_step(py, wa, wb, accA, accB);
        py += 32;
    }

    float4 r0 = { fmaxf(accA[0], 0.f), fmaxf(accA[1], 0.f),
                  fmaxf(accA[2], 0.f), fmaxf(accA[3], 0.f) };
    float4 r1 = { fmaxf(accB[0], 0.f), fmaxf(accB[1], 0.f),
                  fmaxf(accB[2], 0.f), fmaxf(accB[3], 0.f) };
    *(float4*)(outh + j0 * ROWS + half * 4) = r0;
    *(float4*)(outh + (j0 + HN) * ROWS + half * 4) = r1;
}

__device__ __forceinline__ void l3_step(const float* __restrict__ py,
                                        const float4 w,
                                        float* __restrict__ acc) {
#pragma unroll
    for (int q = 0; q < 4; q++) {
        float4 ya = *(const float4*)(py + q * 8);
        float wv = (q == 0) ? w.x : (q == 1) ? w.y : (q == 2) ? w.z : w.w;
        acc[0] = fmaf(ya.x, wv, acc[0]); acc[1] = fmaf(ya.y, wv, acc[1]);
        acc[2] = fmaf(ya.z, wv, acc[2]); acc[3] = fmaf(ya.w, wv, acc[3]);
    }
}

// Layer 3: thread (j, half) computes col j for its 4 rows; result in regs.
__device__ __forceinline__ void layer3(const float* __restrict__ in,
                                       float* __restrict__ k_out,   // [4]
                                       const float* __restrict__ sbias,
                                       int j, int half) {
    constexpr int K4 = HH / 4;
    float acc[4];
    const float bv = sbias[j];
#pragma unroll
    for (int r = 0; r < 4; r++) acc[r] = bv;

    const float* py = in + half * 4;
    const float4* pw = g_W3p + j;
#pragma unroll 4
    for (int i = 0; i < K4; i++) {
        float4 w = pw[0];
        pw += DD;
        l3_step(py, w, acc);
        py += 32;
    }

    k_out[0] = acc[0]; k_out[1] = acc[1]; k_out[2] = acc[2]; k_out[3] = acc[3];
}

__global__ void __launch_bounds__(NT, 1)
ode_kernel(const float* __restrict__ x0,
           const int* __restrict__ Tp,
           const float* __restrict__ b1,
           const float* __restrict__ b2,
           const float* __restrict__ b3,
           float* __restrict__ out,
           int rows_total) {
    extern __shared__ float sm[];
    float* s_y   = sm;                         // DD*8, transposed [d][8]
    float* s_in  = s_y  + ROWS * DD;           // stage input buffer
    float* s_h1  = s_in + ROWS * DD;           // HH*8
    float* s_h2  = s_h1 + ROWS * HH;           // HH*8
    float* s_b1  = s_h2 + ROWS * HH;           // HH
    float* s_b2  = s_b1 + HH;                  // HH
    float* s_b3  = s_b2 + HH;                  // DD

    const int t = threadIdx.x;
    const int j0 = t & 255;                    // col group (layers 1/2: cols j0, j0+HN)
    const int half = t >> 8;                   // row half (rows half*4..half*4+3)
    const int row0 = blockIdx.x * ROWS;
    const int eoff = j0 * ROWS + half * 4;     // this thread's 4 state elems (d=j0)

    const int T = *Tp;
    const int nint = T - 1;
    const float hs = (float)(10.0 / (double)(nint * 4));

    const float A21 = (float)(1.0 / 5.0);
    const float A31 = (float)(3.0 / 40.0),       A32 = (float)(9.0 / 40.0);
    const float A41 = (float)(44.0 / 45.0),      A42 = (float)(-56.0 / 15.0),
                A43 = (float)(32.0 / 9.0);
    const float A51 = (float)(19372.0 / 6561.0), A52 = (float)(-25360.0 / 2187.0),
                A53 = (float)(64448.0 / 6561.0), A54 = (float)(-212.0 / 729.0);
    const float A61 = (float)(9017.0 / 3168.0),  A62 = (float)(-355.0 / 33.0),
                A63 = (float)(46732.0 / 5247.0), A64 = (float)(49.0 / 176.0),
                A65 = (float)(-5103.0 / 18656.0);
    const float B1 = (float)(35.0 / 384.0),  B3 = (float)(500.0 / 1113.0),
                B4 = (float)(125.0 / 192.0), B5 = (float)(-2187.0 / 6784.0),
                B6 = (float)(11.0 / 84.0);

    for (int i = t; i < HH; i += NT) { s_b1[i] = b1[i]; s_b2[i] = b2[i]; }
    for (int i = t; i < DD; i += NT) s_b3[i] = b3[i];
    for (int i = t; i < ROWS * DD; i += NT) {
        int d = i >> 3, r = i & 7;
        s_y[i] = (row0 + r < rows_total) ? x0[(size_t)(row0 + r) * DD + d] : 0.0f;
    }
    __syncthreads();

    // this thread's 4 y-elements live in registers across the whole run
    float y0[4];
    { float4 v = *(const float4*)(s_y + eoff); y0[0]=v.x; y0[1]=v.y; y0[2]=v.z; y0[3]=v.w; }

    float k1[4], k2[4], k3[4], k4[4], k5[4], k6[4];

    for (int it = 0; it < nint; it++) {
        for (int ss = 0; ss < 4; ss++) {
            // ---- stage 1: k1 = f(y) ----
            layer12<DD, HH>(s_y, s_h1, g_W1p, s_b1, j0, half);
            __syncthreads();
            layer12<HH, HH>(s_h1, s_h2, g_W2p, s_b2, j0, half);
            __syncthreads();
            layer3(s_h2, k1, s_b3, j0, half);
            {
                const float c1 = hs * A21;
                float4 v;
#pragma unroll
                for (int p = 0; p < 4; p++)
                    (&v.x)[p] = fmaf(c1, k1[p], y0[p]);
                *(float4*)(s_in + eoff) = v;
            }
            __syncthreads();

            // ---- stage 2 ----
            layer12<DD, HH>(s_in, s_h1, g_W1p, s_b1, j0, half);
            __syncthreads();
            layer12<HH, HH>(s_h1, s_h2, g_W2p, s_b2, j0, half);
            __syncthreads();
            layer3(s_h2, k2, s_b3, j0, half);
            {
                float4 v;
#pragma unroll
                for (int p = 0; p < 4; p++) {
                    float s = fmaf(A31, k1[p], A32 * k2[p]);
                    (&v.x)[p] = fmaf(hs, s, y0[p]);
                }
                *(float4*)(s_in + eoff) = v;
            }
            __syncthreads();

            // ---- stage 3 ----
            layer12<DD, HH>(s_in, s_h1, g_W1p, s_b1, j0, half);
            __syncthreads();
            layer12<HH, HH>(s_h1, s_h2, g_W2p, s_b2, j0, half);
            __syncthreads();
            layer3(s_h2, k3, s_b3, j0, half);
            {
                float4 v;
#pragma unroll
                for (int p = 0; p < 4; p++) {
                    float s = fmaf(A41, k1[p], fmaf(A42, k2[p], A43 * k3[p]));
                    (&v.x)[p] = fmaf(hs, s, y0[p]);
                }
                *(float4*)(s_in + eoff) = v;
            }
            __syncthreads();

            // ---- stage 4 ----
            layer12<DD, HH>(s_in, s_h1, g_W1p, s_b1, j0, half);
            __syncthreads();
            layer12<HH, HH>(s_h1, s_h2, g_W2p, s_b2, j0, half);
            __syncthreads();
            layer3(s_h2, k4, s_b3, j0, half);
            {
                float4 v;
#pragma unroll
                for (int p = 0; p < 4; p++) {
                    float s = fmaf(A51, k1[p],
                              fmaf(A52, k2[p],
                              fmaf(A53, k3[p], A54 * k4[p])));
                    (&v.x)[p] = fmaf(hs, s, y0[p]);
                }
                *(float4*)(s_in + eoff) = v;
            }
            __syncthreads();

            // ---- stage 5 ----
            layer12<DD, HH>(s_in, s_h1, g_W1p, s_b1, j0, half);
            __syncthreads();
            layer12<HH, HH>(s_h1, s_h2, g_W2p, s_b2, j0, half);
            __syncthreads();
            layer3(s_h2, k5, s_b3, j0, half);
            {
                float4 v;
#pragma unroll
                for (int p = 0; p < 4; p++) {
                    float s = fmaf(A61, k1[p],
                              fmaf(A62, k2[p],
                              fmaf(A63, k3[p],
                              fmaf(A64, k4[p], A65 * k5[p]))));
                    (&v.x)[p] = fmaf(hs, s, y0[p]);
                }
                *(float4*)(s_in + eoff) = v;
            }
            __syncthreads();

            // ---- stage 6: k6, then y update ----
            layer12<DD, HH>(s_in, s_h1, g_W1p, s_b1, j0, half);
            __syncthreads();
            layer12<HH, HH>(s_h1, s_h2, g_W2p, s_b2, j0, half);
            __syncthreads();
            layer3(s_h2, k6, s_b3, j0, half);
            {
                float4 v;
#pragma unroll
                for (int p = 0; p < 4; p++) {
                    float s = fmaf(B1, k1[p],
                              fmaf(B3, k3[p],
                              fmaf(B4, k4[p],
                              fmaf(B5, k5[p], B6 * k6[p]))));
                    y0[p] = fmaf(hs, s, y0[p]);
                    (&v.x)[p] = y0[p];
                }
                *(float4*)(s_y + eoff) = v;
            }
            __syncthreads();
        }
        // store y for this interval straight from registers:
        // element (d=j0, r=half*4+p) -> out[(row0+r)*nint + it][d]
#pragma unroll
        for (int p = 0; p < 4; p++) {
            int b = row0 + half * 4 + p;
            if (b < rows_total)
                out[((size_t)b * nint + it) * DD + j0] = y0[p];
        }
    }
}

extern "C" void kernel_launch(void* const* d_in, const int* in_sizes, int n_in,
                              void* d_out, int out_size) {
    const float* x0 = (const float*)d_in[0];
    const int*   Tp = (const int*)d_in[1];
    const float* W1 = (const float*)d_in[2];
    const float* b1 = (const float*)d_in[3];
    const float* W2 = (const float*)d_in[4];
    const float* b2 = (const float*)d_in[5];
    const float* W3 = (const float*)d_in[6];
    const float* b3 = (const float*)d_in[7];
    float* out = (float*)d_out;

    int rows_total = in_sizes[0] / DD;          // B
    int nblocks = (rows_total + ROWS - 1) / ROWS;

    size_t smem = (size_t)(2 * ROWS * DD + 2 * ROWS * HH + 2 * HH + DD) * sizeof(float);
    cudaFuncSetAttribute(ode_kernel, cudaFuncAttributeMaxDynamicSharedMemorySize,
                         (int)smem);

    prep_kernel<<<64, 256>>>(W1, W2, W3);
    ode_kernel<<<nblocks, NT, smem>>>(x0, Tp, b1, b2, b3, out, rows_total);
}